// round 12
// baseline (speedup 1.0000x reference)
#include <cuda_runtime.h>
#include <math.h>
#include <stdint.h>

#define Bdim 128
#define Hdim 512
#define Ldim 256
#define OUTdim 256
#define NCTA 128

// ---------------- persistent state & precomputed sequences ------------------
__device__ __align__(128) float g_xmeanBH[Bdim*Hdim];               // [b][h]
__device__ __align__(128) float g_dtT   [Ldim*Bdim];
__device__ __align__(128) float g_hsT   [Hdim*Bdim];                // h_scaled (recurrent) [h][b]
__device__ __align__(128) float g_rhT   [Hdim*Bdim];
__device__ __align__(128) float g_maskf [(size_t)Bdim*Ldim*Hdim];   // mask as float [b][i][h]
__device__ __align__(128) float g_xhatS [(size_t)Ldim*Bdim*Hdim];   // x_hat [i][b][h] (tf32-rounded)
__device__ __align__(128) float g_deltaS[(size_t)Ldim*Bdim*Hdim];   // delta [i][b][h] (tf32-rounded)
__device__ __align__(128) float g_preZ  [(size_t)Ldim*2*Hdim*Bdim]; // zr pre-act (+bias) [i][col][b]
__device__ __align__(128) float g_preC  [(size_t)Ldim*Hdim*Bdim];   // cand pre-act (+bias) [i][col][b]
__device__ __align__(128) float g_gamma [(size_t)Ldim*Hdim*Bdim];   // gamma_h [i][col][b]
__device__ __align__(128) float g_hseq  [(size_t)Ldim*Hdim*Bdim];   // recurrence outputs [i][h][b]
// tf32-pre-rounded weight copies
__device__ __align__(128) float g_WxR [Hdim*3*Hdim];
__device__ __align__(128) float g_WmR [Hdim*3*Hdim];
__device__ __align__(128) float g_WhR [Hdim*3*Hdim];
__device__ __align__(128) float g_WghR[Hdim*Hdim];
// per-batch-group barrier state
__device__ unsigned g_bgbar_count[4];
__device__ unsigned g_bgbar_epoch[4];

// ---------------- cp.async helpers ------------------------------------------
__device__ __forceinline__ void cp16(void* s, const void* g) {
    unsigned sa = (unsigned)__cvta_generic_to_shared(s);
    asm volatile("cp.async.cg.shared.global [%0], [%1], 16;\n" :: "r"(sa), "l"(g));
}
#define CP_COMMIT asm volatile("cp.async.commit_group;\n" ::: "memory")
#define CP_WAIT1  asm volatile("cp.async.wait_group 1;\n" ::: "memory")
#define CP_WAIT0  asm volatile("cp.async.wait_group 0;\n" ::: "memory")

// ---------------- tf32 mma helpers ------------------------------------------
__device__ __forceinline__ unsigned f2tf32(float x) {
    unsigned r;
    asm("cvt.rna.tf32.f32 %0, %1;" : "=r"(r) : "f"(x));
    return r;
}
__device__ __forceinline__ void mma_tf32(float c[4],
    unsigned a0, unsigned a1, unsigned a2, unsigned a3,
    unsigned b0, unsigned b1) {
    asm volatile(
        "mma.sync.aligned.m16n8k8.row.col.f32.tf32.tf32.f32 "
        "{%0,%1,%2,%3}, {%4,%5,%6,%7}, {%8,%9}, {%0,%1,%2,%3};"
        : "+f"(c[0]), "+f"(c[1]), "+f"(c[2]), "+f"(c[3])
        : "r"(a0), "r"(a1), "r"(a2), "r"(a3), "r"(b0), "r"(b1));
}

// ---------------- per-batch-group barrier (32 CTAs each, hot spin) -----------
__device__ __forceinline__ void bg_barrier(int bg, unsigned &epoch) {
    __threadfence();
    __syncthreads();
    if (threadIdx.x == 0) {
        unsigned old = atomicAdd(&g_bgbar_count[bg], 1);
        if (old == 31) {
            g_bgbar_count[bg] = 0;
            __threadfence();
            atomicAdd(&g_bgbar_epoch[bg], 1);
        } else {
            while (*(volatile unsigned*)&g_bgbar_epoch[bg] == epoch) { }
        }
    }
    epoch++;
    __syncthreads();
}

// ---------------- setup: maskf, x_mean, dt, barrier reset --------------------
__global__ void k_setup(const float* __restrict__ C, const float* __restrict__ t,
                        const int* __restrict__ mask) {
    int b = blockIdx.x;
    int h = threadIdx.x;                 // 512
    float s1 = 0.f, s0 = 0.f;
    for (int i = 0; i < Ldim; i++) {
        size_t mi = ((size_t)b*Ldim + i)*Hdim + h;
        float m = (float)mask[mi];
        g_maskf[mi] = m;
        s1 += m * C[i*Hdim + h];
        s0 += m;
    }
    g_xmeanBH[b*Hdim + h] = s1 / fmaxf(s0, 1.f);
    if (h < Ldim) {
        int i = h;
        g_dtT[i*Bdim + b] = (i == 0) ? 0.f : (t[b*Ldim + i] - t[b*Ldim + i - 1]);
    }
    if (b == 0 && h < 4) { g_bgbar_count[h] = 0; g_bgbar_epoch[h] = 0; }
}

// ---------------- round weights to tf32 once ---------------------------------
__global__ void __launch_bounds__(1024) k_roundw(const float* __restrict__ Wx,
                                                 const float* __restrict__ Wm,
                                                 const float* __restrict__ Wh,
                                                 const float* __restrict__ Wgh) {
    int idx = blockIdx.x * 1024 + threadIdx.x;       // grid covers 786432
    g_WxR[idx] = __uint_as_float(f2tf32(Wx[idx]));
    g_WmR[idx] = __uint_as_float(f2tf32(Wm[idx]));
    g_WhR[idx] = __uint_as_float(f2tf32(Wh[idx]));
    if (idx < Hdim*Hdim)
        g_WghR[idx] = __uint_as_float(f2tf32(Wgh[idx]));
}

// ---------------- elementwise scan: delta[i], x_hat[i] (tf32-rounded) --------
__global__ void __launch_bounds__(512) k_scan(const float* __restrict__ C,
                                              const float* __restrict__ w_gx,
                                              const float* __restrict__ b_gx) {
    int gid = blockIdx.x * 512 + threadIdx.x;   // 65536
    int b = gid >> 9, h = gid & 511;
    float xm = g_xmeanBH[b*Hdim + h];
    float x_last = xm, delta = 0.f, m_prev = 1.f;
    float wg = __ldg(&w_gx[h]), bg = __ldg(&b_gx[h]);
    for (int i = 0; i < Ldim; i++) {
        float dti = g_dtT[i*Bdim + b];
        delta = dti + (1.f - m_prev) * delta;
        float m  = g_maskf[((size_t)b*Ldim + i)*Hdim + h];
        float xi = __ldg(&C[i*Hdim + h]);
        float gx = __expf(-fmaxf(0.f, wg*delta + bg));
        size_t idx = ((size_t)i*Bdim + b)*Hdim + h;
        float xh = m*xi + (1.f - m)*(gx*x_last + (1.f - gx)*xm);
        g_xhatS[idx]  = __uint_as_float(f2tf32(xh));
        g_deltaS[idx] = __uint_as_float(f2tf32(delta));
        x_last = m*xi + (1.f - m)*x_last;
        m_prev = m;
    }
    g_hsT[h*Bdim + b] = 0.f;   // h_scaled init (h0 = 0)
}

// ---------------- tf32 tensor GEMM: pre = [xhat;m] @ [Wx;Wm] + b -------------
// 3-buffer, depth-2 cp.async pipeline, ONE __syncthreads per K-iter.
#define PAD_A 36
#define PAD_B 136
#define PRE_SMEM ((3*128*PAD_A + 3*32*PAD_B)*4)
__global__ void __launch_bounds__(256, 2) k_pre(const float* __restrict__ bvec) {
    extern __shared__ float sm[];
    float* sA = sm;                     // 3 x 128 x 36
    float* sB = sm + 3*128*PAD_A;       // 3 x 32 x 136
    int ct = blockIdx.x, i = blockIdx.y, tid = threadIdx.x;
    int lane = tid & 31, warp = tid >> 5;
    int wm = warp & 1, wn = warp >> 1;

    auto loadA = [&](int ck, int buf) {
        int k0 = ck*32;
#pragma unroll
        for (int v = 0; v < 4; v++) {
            int idx = tid + v*256;
            int b = idx >> 3;
            int kq = (idx & 7) * 4;
            const float* src = (k0 < Hdim)
                ? g_xhatS + ((size_t)i*Bdim + b)*Hdim + k0 + kq
                : g_maskf + ((size_t)b*Ldim + i)*Hdim + (k0 - Hdim) + kq;
            cp16(sA + buf*128*PAD_A + b*PAD_A + kq, src);
        }
    };
    auto loadB = [&](int ck, int buf) {
        int k0 = ck*32;
#pragma unroll
        for (int v = 0; v < 4; v++) {
            int idx = tid + v*256;
            int k = idx >> 5;
            int q = (idx & 31) * 4;
            const float* src = (k0 < Hdim
                ? g_WxR + (size_t)(k0 + k)*1536
                : g_WmR + (size_t)(k0 - Hdim + k)*1536) + ct*128 + q;
            cp16(sB + buf*32*PAD_B + k*PAD_B + q, src);
        }
    };

    float c[4][4][4] = {};
    loadA(0, 0); loadB(0, 0); CP_COMMIT;
    loadA(1, 1); loadB(1, 1); CP_COMMIT;
    for (int ck = 0; ck < 32; ck++) {
        if (ck < 31) { CP_WAIT1; } else { CP_WAIT0; }
        __syncthreads();                 // group(ck) visible; compute(ck-1) done
        if (ck + 2 < 32) {
            loadA(ck+2, (ck+2)%3); loadB(ck+2, (ck+2)%3); CP_COMMIT;
        }
        const float* A = sA + (ck%3)*128*PAD_A;
        const float* B = sB + (ck%3)*32*PAD_B;
#pragma unroll
        for (int ks = 0; ks < 4; ks++) {
            unsigned af[4][4], bf[4][2];
#pragma unroll
            for (int mi = 0; mi < 4; mi++) {
                int r  = wm*64 + mi*16 + (lane >> 2);
                int cc = ks*8 + (lane & 3);
                af[mi][0] = __float_as_uint(A[r*PAD_A + cc]);
                af[mi][1] = __float_as_uint(A[(r+8)*PAD_A + cc]);
                af[mi][2] = __float_as_uint(A[r*PAD_A + cc + 4]);
                af[mi][3] = __float_as_uint(A[(r+8)*PAD_A + cc + 4]);
            }
#pragma unroll
            for (int ni = 0; ni < 4; ni++) {
                int n  = wn*32 + ni*8 + (lane >> 2);
                int kk = ks*8 + (lane & 3);
                bf[ni][0] = __float_as_uint(B[kk*PAD_B + n]);
                bf[ni][1] = __float_as_uint(B[(kk+4)*PAD_B + n]);
            }
#pragma unroll
            for (int mi = 0; mi < 4; mi++)
#pragma unroll
                for (int ni = 0; ni < 4; ni++)
                    mma_tf32(c[mi][ni], af[mi][0], af[mi][1], af[mi][2], af[mi][3],
                             bf[ni][0], bf[ni][1]);
        }
    }
#pragma unroll
    for (int mi = 0; mi < 4; mi++) {
        int r0 = wm*64 + mi*16 + (lane >> 2);
#pragma unroll
        for (int ni = 0; ni < 4; ni++) {
            int col0 = ct*128 + wn*32 + ni*8 + (lane & 3)*2;
            float bv0 = __ldg(&bvec[col0]);
            float bv1 = __ldg(&bvec[col0 + 1]);
            float* d0;
            float* d1;
            if (ct < 8) {
                d0 = g_preZ + (size_t)i*(2*Hdim*Bdim) + (size_t)col0*Bdim;
                d1 = d0 + Bdim;
            } else {
                d0 = g_preC + (size_t)i*(Hdim*Bdim) + (size_t)(col0 - 2*Hdim)*Bdim;
                d1 = d0 + Bdim;
            }
            d0[r0]     = c[mi][ni][0] + bv0;
            d1[r0]     = c[mi][ni][1] + bv1;
            d0[r0 + 8] = c[mi][ni][2] + bv0;
            d1[r0 + 8] = c[mi][ni][3] + bv1;
        }
    }
}

// ---------------- tf32 tensor GEMM: gamma = exp(-relu(delta@Wgh + b)) --------
__global__ void __launch_bounds__(256, 2) k_gamma(const float* __restrict__ bgh) {
    extern __shared__ float sm[];
    float* sA = sm;
    float* sB = sm + 3*128*PAD_A;
    int ct = blockIdx.x, i = blockIdx.y, tid = threadIdx.x;
    int lane = tid & 31, warp = tid >> 5;
    int wm = warp & 1, wn = warp >> 1;

    auto loadA = [&](int ck, int buf) {
        int k0 = ck*32;
#pragma unroll
        for (int v = 0; v < 4; v++) {
            int idx = tid + v*256;
            int b = idx >> 3;
            int kq = (idx & 7) * 4;
            cp16(sA + buf*128*PAD_A + b*PAD_A + kq,
                 g_deltaS + ((size_t)i*Bdim + b)*Hdim + k0 + kq);
        }
    };
    auto loadB = [&](int ck, int buf) {
        int k0 = ck*32;
#pragma unroll
        for (int v = 0; v < 4; v++) {
            int idx = tid + v*256;
            int k = idx >> 5;
            int q = (idx & 31) * 4;
            cp16(sB + buf*32*PAD_B + k*PAD_B + q,
                 g_WghR + (size_t)(k0 + k)*Hdim + ct*128 + q);
        }
    };

    float c[4][4][4] = {};
    loadA(0, 0); loadB(0, 0); CP_COMMIT;
    loadA(1, 1); loadB(1, 1); CP_COMMIT;
    for (int ck = 0; ck < 16; ck++) {
        if (ck < 15) { CP_WAIT1; } else { CP_WAIT0; }
        __syncthreads();
        if (ck + 2 < 16) {
            loadA(ck+2, (ck+2)%3); loadB(ck+2, (ck+2)%3); CP_COMMIT;
        }
        const float* A = sA + (ck%3)*128*PAD_A;
        const float* B = sB + (ck%3)*32*PAD_B;
#pragma unroll
        for (int ks = 0; ks < 4; ks++) {
            unsigned af[4][4], bf[4][2];
#pragma unroll
            for (int mi = 0; mi < 4; mi++) {
                int r  = wm*64 + mi*16 + (lane >> 2);
                int cc = ks*8 + (lane & 3);
                af[mi][0] = __float_as_uint(A[r*PAD_A + cc]);
                af[mi][1] = __float_as_uint(A[(r+8)*PAD_A + cc]);
                af[mi][2] = __float_as_uint(A[r*PAD_A + cc + 4]);
                af[mi][3] = __float_as_uint(A[(r+8)*PAD_A + cc + 4]);
            }
#pragma unroll
            for (int ni = 0; ni < 4; ni++) {
                int n  = wn*32 + ni*8 + (lane >> 2);
                int kk = ks*8 + (lane & 3);
                bf[ni][0] = __float_as_uint(B[kk*PAD_B + n]);
                bf[ni][1] = __float_as_uint(B[(kk+4)*PAD_B + n]);
            }
#pragma unroll
            for (int mi = 0; mi < 4; mi++)
#pragma unroll
                for (int ni = 0; ni < 4; ni++)
                    mma_tf32(c[mi][ni], af[mi][0], af[mi][1], af[mi][2], af[mi][3],
                             bf[ni][0], bf[ni][1]);
        }
    }
#pragma unroll
    for (int mi = 0; mi < 4; mi++) {
        int r0 = wm*64 + mi*16 + (lane >> 2);
#pragma unroll
        for (int ni = 0; ni < 4; ni++) {
            int col0 = ct*128 + wn*32 + ni*8 + (lane & 3)*2;
            float bv0 = __ldg(&bgh[col0]);
            float bv1 = __ldg(&bgh[col0 + 1]);
            float* d0 = g_gamma + (size_t)i*(Hdim*Bdim) + (size_t)col0*Bdim;
            float* d1 = d0 + Bdim;
            d0[r0]     = __expf(-fmaxf(0.f, c[mi][ni][0] + bv0));
            d1[r0]     = __expf(-fmaxf(0.f, c[mi][ni][1] + bv1));
            d0[r0 + 8] = __expf(-fmaxf(0.f, c[mi][ni][2] + bv0));
            d1[r0 + 8] = __expf(-fmaxf(0.f, c[mi][ni][3] + bv1));
        }
    }
}

// ============ persistent recurrence: tensor-core, 2xTF32, paired z/r =========
// 128 CTAs = 4 batch groups (32 batches) x 32 col groups.
// CTA cg owns z col (16cg+j), r col (512+16cg+j), cand col (1024+16cg+j), j<16.
#define SWH(k,b) ((k)*32 + ((b) ^ (((k)&3)<<3)))
#define SW3(k,n) ((k)*16 + ((n) ^ (((k)&2)<<2)))
#define OFF_H    0
#define OFF_WZR  16384
#define OFF_W3   32768
#define OFF_PART 40960
#define OFF_PZ   49408
#define OFF_PC   50432
#define OFF_GAM  50944
#define MAIN_SM_FLOATS 51456   // ~201 KB

__global__ void __launch_bounds__(512, 1) k_main() {
    extern __shared__ float sm[];
    float* smH   = sm + OFF_H;     // [512][32] swizzled (h_s / rh batch slice)
    float* sWzr  = sm + OFF_WZR;   // [512][32] swizzled: cols 0..15 = z, 16..31 = r
    float* sW3   = sm + OFF_W3;    // [512][16] swizzled
    float* sPart = sm + OFF_PART;  // K-group partials
    float* smPZ  = sm + OFF_PZ;    // preZ slice [32col][32b] (z then r cols)
    float* smPC  = sm + OFF_PC;    // preC slice [16col][32b]
    float* smGam = sm + OFF_GAM;   // gamma[i+1] slice [16col][32b]

    const int c   = blockIdx.x;
    const int tid = threadIdx.x;
    const int bg  = c & 3;
    const int cg  = c >> 2;
    const int lane = tid & 31, warp = tid >> 5;
    const int kg = warp >> 1, mh = warp & 1;
    const int r = lane >> 2, q = lane & 3;
    const int t64 = tid & 63;

    // one-time weight slices (pre-rounded tf32)
    for (int f = tid; f < 4096; f += 512) {          // Wh_zr: 512x32 (z|r paired)
        int k = f >> 3, n = (f & 7) * 4;
        int gcol = (n < 16) ? (cg*16 + n) : (512 + cg*16 + (n - 16));
        cp16(&sWzr[SWH(k, n)], &g_WhR[(size_t)k*1536 + gcol]);
    }
    for (int f = tid; f < 2048; f += 512) {          // Wh3: 512x16
        int k = f >> 2, n = (f & 3) * 4;
        cp16(&sW3[SW3(k, n)], &g_WhR[(size_t)k*1536 + 1024 + cg*16 + n]);
    }
    CP_COMMIT; CP_WAIT0;
    __syncthreads();

    unsigned epoch = 0;

    for (int i = 0; i < Ldim; i++) {
        // ---- prefetch step-constant slices ----
        if (tid < 256) {
            int col = tid >> 3, b4 = (tid & 7) * 4;   // col 0..31 (z|r paired)
            int gcol = (col < 16) ? (cg*16 + col) : (512 + cg*16 + (col - 16));
            cp16(&smPZ[col*32 + b4],
                 &g_preZ[(size_t)i*131072 + (size_t)gcol*128 + bg*32 + b4]);
        } else if (tid < 384) {
            int f = tid - 256;
            int col = f >> 3, b4 = (f & 7) * 4;
            cp16(&smPC[col*32 + b4],
                 &g_preC[(size_t)i*65536 + (size_t)(cg*16 + col)*128 + bg*32 + b4]);
        } else if (i + 1 < Ldim) {
            int f = tid - 384;
            int col = f >> 3, b4 = (f & 7) * 4;
            cp16(&smGam[col*32 + b4],
                 &g_gamma[(size_t)(i+1)*65536 + (size_t)(cg*16 + col)*128 + bg*32 + b4]);
        }
        CP_COMMIT;

        // ---- pipelined stage of h_s: each warp-pair stages only its K-rows ----
#pragma unroll
        for (int j = 0; j < 8; j++) {
            int f = kg*512 + t64 + j*64;
            int k = f >> 3, nb = (f & 7) * 4;
            cp16(&smH[SWH(k, nb)], &g_hsT[k*128 + bg*32 + nb]);
        }
        CP_COMMIT; CP_WAIT0;
        asm volatile("bar.sync %0, 64;" :: "r"(kg + 1) : "memory");

        // ---- phase1 mma (2xTF32): C[32b x 32col(z|r)], hi pass then lo pass ----
        {
            float acc[4][4] = {};
#pragma unroll
            for (int ks = 0; ks < 8; ks++) {
                int ka = kg*64 + ks*8 + q;
                int kb = ka + 4;
                int row = mh*16 + r;
                float a0f = smH[SWH(ka, row)];
                float a1f = smH[SWH(ka, row + 8)];
                float a2f = smH[SWH(kb, row)];
                float a3f = smH[SWH(kb, row + 8)];
                unsigned ah0 = f2tf32(a0f), ah1 = f2tf32(a1f);
                unsigned ah2 = f2tf32(a2f), ah3 = f2tf32(a3f);
                unsigned bh0[4], bh1[4];
#pragma unroll
                for (int nt = 0; nt < 4; nt++) {
                    int n = nt*8 + r;
                    bh0[nt] = __float_as_uint(sWzr[SWH(ka, n)]);
                    bh1[nt] = __float_as_uint(sWzr[SWH(kb, n)]);
                }
#pragma unroll
                for (int nt = 0; nt < 4; nt++)
                    mma_tf32(acc[nt], ah0, ah1, ah2, ah3, bh0[nt], bh1[nt]);
                unsigned al0 = f2tf32(a0f - __uint_as_float(ah0));
                unsigned al1 = f2tf32(a1f - __uint_as_float(ah1));
                unsigned al2 = f2tf32(a2f - __uint_as_float(ah2));
                unsigned al3 = f2tf32(a3f - __uint_as_float(ah3));
#pragma unroll
                for (int nt = 0; nt < 4; nt++)
                    mma_tf32(acc[nt], al0, al1, al2, al3, bh0[nt], bh1[nt]);
            }
            float* P = sPart + kg*1056;
            int row = mh*16 + r;
#pragma unroll
            for (int nt = 0; nt < 4; nt++) {
                int col = nt*8 + 2*q;
                P[row*33 + col]       = acc[nt][0];
                P[row*33 + col + 1]   = acc[nt][1];
                P[(row+8)*33 + col]   = acc[nt][2];
                P[(row+8)*33 + col+1] = acc[nt][3];
            }
        }
        __syncthreads();
        // reduce 8 partials + activation; z and own h_s stay in registers
        float zreg, hsreg;
        {
            // o = 0: z col (col = warp)
            float s = 0.f;
#pragma unroll
            for (int g2 = 0; g2 < 8; g2++)
                s += sPart[g2*1056 + lane*33 + warp];
            s += smPZ[warp*32 + lane];
            zreg = 1.f / (1.f + __expf(-s));
            // o = 1: r col (col = warp + 16) -> rh = r * h_s[own col]
            float s2 = 0.f;
#pragma unroll
            for (int g2 = 0; g2 < 8; g2++)
                s2 += sPart[g2*1056 + lane*33 + warp + 16];
            s2 += smPZ[(warp + 16)*32 + lane];
            float rg = 1.f / (1.f + __expf(-s2));
            hsreg = smH[SWH(cg*16 + warp, lane)];
            g_rhT[(cg*16 + warp)*128 + bg*32 + lane] = rg * hsreg;
        }
        bg_barrier(bg, epoch);

        // ---- pipelined stage of rh ----
#pragma unroll
        for (int j = 0; j < 8; j++) {
            int f = kg*512 + t64 + j*64;
            int k = f >> 3, nb = (f & 7) * 4;
            cp16(&smH[SWH(k, nb)], &g_rhT[k*128 + bg*32 + nb]);
        }
        CP_COMMIT; CP_WAIT0;
        asm volatile("bar.sync %0, 64;" :: "r"(kg + 1) : "memory");

        // ---- phase2 mma (2xTF32): C[32b x 16col], hi pass then lo pass ----
        {
            float acc[2][4] = {};
#pragma unroll
            for (int ks = 0; ks < 8; ks++) {
                int ka = kg*64 + ks*8 + q;
                int kb = ka + 4;
                int row = mh*16 + r;
                float a0f = smH[SWH(ka, row)];
                float a1f = smH[SWH(ka, row + 8)];
                float a2f = smH[SWH(kb, row)];
                float a3f = smH[SWH(kb, row + 8)];
                unsigned ah0 = f2tf32(a0f), ah1 = f2tf32(a1f);
                unsigned ah2 = f2tf32(a2f), ah3 = f2tf32(a3f);
                unsigned bh0[2], bh1[2];
#pragma unroll
                for (int nt = 0; nt < 2; nt++) {
                    int n = nt*8 + r;
                    bh0[nt] = __float_as_uint(sW3[SW3(ka, n)]);
                    bh1[nt] = __float_as_uint(sW3[SW3(kb, n)]);
                }
#pragma unroll
                for (int nt = 0; nt < 2; nt++)
                    mma_tf32(acc[nt], ah0, ah1, ah2, ah3, bh0[nt], bh1[nt]);
                unsigned al0 = f2tf32(a0f - __uint_as_float(ah0));
                unsigned al1 = f2tf32(a1f - __uint_as_float(ah1));
                unsigned al2 = f2tf32(a2f - __uint_as_float(ah2));
                unsigned al3 = f2tf32(a3f - __uint_as_float(ah3));
#pragma unroll
                for (int nt = 0; nt < 2; nt++)
                    mma_tf32(acc[nt], al0, al1, al2, al3, bh0[nt], bh1[nt]);
            }
            float* P = sPart + kg*544;
            int row = mh*16 + r;
#pragma unroll
            for (int nt = 0; nt < 2; nt++) {
                int col = nt*8 + 2*q;
                P[row*17 + col]       = acc[nt][0];
                P[row*17 + col + 1]   = acc[nt][1];
                P[(row+8)*17 + col]   = acc[nt][2];
                P[(row+8)*17 + col+1] = acc[nt][3];
            }
        }
        __syncthreads();
        // reduce + h update (col = warp, b = lane; z/h_s are registers)
        {
            float s = 0.f;
#pragma unroll
            for (int g2 = 0; g2 < 8; g2++)
                s += sPart[g2*544 + lane*17 + warp];
            float ht = tanhf(s + smPC[warp*32 + lane]);
            float hn = (1.f - zreg)*hsreg + zreg*ht;
            int gi = (cg*16 + warp)*128 + bg*32 + lane;
            g_hseq[(size_t)i*65536 + gi] = hn;
            if (i + 1 < Ldim)
                g_hsT[gi] = hn * smGam[warp*32 + lane];
        }
        bg_barrier(bg, epoch);
    }
}

// ---------------- tf32 output GEMM: out = h_seq @ W_out + b_out --------------
#define OUT_SMEM (3*(4096+4096)*4)
__global__ void __launch_bounds__(256, 2) k_out(const float* __restrict__ Wout,
                                                const float* __restrict__ bout,
                                                float* __restrict__ out) {
    extern __shared__ float sm[];
    float* sA = sm;            // 3 x [32k][128b] swizzled
    float* sB = sm + 3*4096;   // 3 x [32k][128n] swizzled
    int ct = blockIdx.x, i = blockIdx.y, tid = threadIdx.x;
    int lane = tid & 31, warp = tid >> 5;
    int wm = warp & 1, wn = warp >> 1;

    auto loadA = [&](int ck, int buf) {
#pragma unroll
        for (int v = 0; v < 4; v++) {
            int f = tid + v*256;
            int k = f >> 5, nb = (f & 31) * 4;
            cp16(&sA[buf*4096 + k*128 + (nb ^ ((k & 3) << 3))],
                 &g_hseq[(size_t)i*65536 + (size_t)(ck*32 + k)*128 + nb]);
        }
    };
    auto loadB = [&](int ck, int buf) {
#pragma unroll
        for (int v = 0; v < 4; v++) {
            int f = tid + v*256;
            int k = f >> 5, nb = (f & 31) * 4;
            cp16(&sB[buf*4096 + k*128 + (nb ^ ((k & 3) << 3))],
                 &Wout[(size_t)(ck*32 + k)*OUTdim + ct*128 + nb]);
        }
    };

    float c[4][4][4] = {};
    loadA(0, 0); loadB(0, 0); CP_COMMIT;
    loadA(1, 1); loadB(1, 1); CP_COMMIT;
    for (int ck = 0; ck < 16; ck++) {
        if (ck < 15) { CP_WAIT1; } else { CP_WAIT0; }
        __syncthreads();
        if (ck + 2 < 16) { loadA(ck+2, (ck+2)%3); loadB(ck+2, (ck+2)%3); CP_COMMIT; }
        const float* A = sA + (ck%3)*4096;
        const float* B = sB + (ck%3)*4096;
#pragma unroll
        for (int ks = 0; ks < 4; ks++) {
            int ka = ks*8 + (lane & 3);
            int kb = ka + 4;
            unsigned af[4][4], bf[4][2];
#pragma unroll
            for (int mi = 0; mi < 4; mi++) {
                int b0 = wm*64 + mi*16 + (lane >> 2);
                af[mi][0] = f2tf32(A[ka*128 + (b0 ^ ((ka & 3) << 3))]);
                af[mi][1] = f2tf32(A[ka*128 + ((b0+8) ^ ((ka & 3) << 3))]);
                af[mi][2] = f2tf32(A[kb*128 + (b0 ^ ((kb & 3) << 3))]);
                af[mi][3] = f2tf32(A[kb*128 + ((b0+8) ^ ((kb & 3) << 3))]);
            }
#pragma unroll
            for (int ni = 0; ni < 4; ni++) {
                int n = wn*32 + ni*8 + (lane >> 2);
                bf[ni][0] = f2tf32(B[ka*128 + (n ^ ((ka & 3) << 3))]);
                bf[ni][1] = f2tf32(B[kb*128 + (n ^ ((kb & 3) << 3))]);
            }
#pragma unroll
            for (int mi = 0; mi < 4; mi++)
#pragma unroll
                for (int ni = 0; ni < 4; ni++)
                    mma_tf32(c[mi][ni], af[mi][0], af[mi][1], af[mi][2], af[mi][3],
                             bf[ni][0], bf[ni][1]);
        }
    }
#pragma unroll
    for (int mi = 0; mi < 4; mi++) {
        int r0 = wm*64 + mi*16 + (lane >> 2);
#pragma unroll
        for (int ni = 0; ni < 4; ni++) {
            int o0 = ct*128 + wn*32 + ni*8 + (lane & 3)*2;
            float bv0 = __ldg(&bout[o0]);
            float bv1 = __ldg(&bout[o0 + 1]);
            out[((size_t)r0*Ldim + i)*OUTdim + o0]         = c[mi][ni][0] + bv0;
            out[((size_t)r0*Ldim + i)*OUTdim + o0 + 1]     = c[mi][ni][1] + bv1;
            out[((size_t)(r0+8)*Ldim + i)*OUTdim + o0]     = c[mi][ni][2] + bv0;
            out[((size_t)(r0+8)*Ldim + i)*OUTdim + o0 + 1] = c[mi][ni][3] + bv1;
        }
    }
}

// ---------------- launch ------------------------------------------------------
extern "C" void kernel_launch(void* const* d_in, const int* in_sizes, int n_in,
                              void* d_out, int out_size) {
    const float* C    = (const float*)d_in[0];
    const float* t    = (const float*)d_in[1];
    const int*   mask = (const int*)  d_in[2];
    const float* Wx   = (const float*)d_in[3];
    const float* Wh   = (const float*)d_in[4];
    const float* Wm   = (const float*)d_in[5];
    const float* bvec = (const float*)d_in[6];
    const float* wgx  = (const float*)d_in[7];
    const float* bgx  = (const float*)d_in[8];
    const float* Wgh  = (const float*)d_in[9];
    const float* bgh  = (const float*)d_in[10];
    const float* Wout = (const float*)d_in[11];
    const float* bout = (const float*)d_in[12];
    float* out = (float*)d_out;

    cudaFuncSetAttribute(k_main, cudaFuncAttributeMaxDynamicSharedMemorySize,
                         MAIN_SM_FLOATS * 4);
    cudaFuncSetAttribute(k_pre, cudaFuncAttributeMaxDynamicSharedMemorySize, PRE_SMEM);
    cudaFuncSetAttribute(k_gamma, cudaFuncAttributeMaxDynamicSharedMemorySize, PRE_SMEM);
    cudaFuncSetAttribute(k_out, cudaFuncAttributeMaxDynamicSharedMemorySize, OUT_SMEM);

    k_setup<<<Bdim, Hdim>>>(C, t, mask);
    k_roundw<<<768, 1024>>>(Wx, Wm, Wh, Wgh);
    k_scan<<<128, 512>>>(C, wgx, bgx);
    k_pre<<<dim3(12, Ldim), 256, PRE_SMEM>>>(bvec);
    k_gamma<<<dim3(4, Ldim), 256, PRE_SMEM>>>(bgh);
    k_main<<<NCTA, 512, MAIN_SM_FLOATS * 4>>>();
    k_out<<<dim3(2, Ldim), 256, OUT_SMEM>>>(Wout, bout, out);
}

// round 16
// speedup vs baseline: 1.0547x; 1.0547x over previous
#include <cuda_runtime.h>
#include <math.h>
#include <stdint.h>

#define Bdim 128
#define Hdim 512
#define Ldim 256
#define OUTdim 256
#define NCTA 128

// ---------------- persistent state & precomputed sequences ------------------
__device__ __align__(128) float g_xmeanBH[Bdim*Hdim];               // [b][h]
__device__ __align__(128) float g_dtT   [Ldim*Bdim];
__device__ __align__(128) float g_hsT   [Hdim*Bdim];                // h_scaled (recurrent) [h][b]
__device__ __align__(128) float g_rhT   [Hdim*Bdim];
__device__ __align__(128) float g_maskf [(size_t)Bdim*Ldim*Hdim];   // mask as float [b][i][h]
__device__ __align__(128) float g_xhatS [(size_t)Ldim*Bdim*Hdim];   // x_hat [i][b][h] (tf32-rounded)
__device__ __align__(128) float g_deltaS[(size_t)Ldim*Bdim*Hdim];   // delta [i][b][h] (tf32-rounded)
__device__ __align__(128) float g_preZ  [(size_t)Ldim*2*Hdim*Bdim]; // zr pre-act (+bias) [i][col][b]
__device__ __align__(128) float g_preC  [(size_t)Ldim*Hdim*Bdim];   // cand pre-act (+bias) [i][col][b]
__device__ __align__(128) float g_gamma [(size_t)Ldim*Hdim*Bdim];   // gamma_h [i][col][b]
__device__ __align__(128) float g_hseq  [(size_t)Ldim*Hdim*Bdim];   // recurrence outputs [i][h][b]
// tf32-pre-rounded weight copies
__device__ __align__(128) float g_WxR [Hdim*3*Hdim];
__device__ __align__(128) float g_WmR [Hdim*3*Hdim];
__device__ __align__(128) float g_WhR [Hdim*3*Hdim];
__device__ __align__(128) float g_WghR[Hdim*Hdim];
// monotone barrier counters (one-hop: RED arrive + volatile poll)
__device__ __align__(128) unsigned g_cnt1[4];
__device__ __align__(128) unsigned g_cnt2[4];

// ---------------- cp.async helpers ------------------------------------------
__device__ __forceinline__ void cp16(void* s, const void* g) {
    unsigned sa = (unsigned)__cvta_generic_to_shared(s);
    asm volatile("cp.async.cg.shared.global [%0], [%1], 16;\n" :: "r"(sa), "l"(g));
}
#define CP_COMMIT asm volatile("cp.async.commit_group;\n" ::: "memory")
#define CP_WAIT1  asm volatile("cp.async.wait_group 1;\n" ::: "memory")
#define CP_WAIT0  asm volatile("cp.async.wait_group 0;\n" ::: "memory")

// ---------------- tf32 mma helpers ------------------------------------------
__device__ __forceinline__ unsigned f2tf32(float x) {
    unsigned r;
    asm("cvt.rna.tf32.f32 %0, %1;" : "=r"(r) : "f"(x));
    return r;
}
__device__ __forceinline__ void mma_tf32(float c[4],
    unsigned a0, unsigned a1, unsigned a2, unsigned a3,
    unsigned b0, unsigned b1) {
    asm volatile(
        "mma.sync.aligned.m16n8k8.row.col.f32.tf32.tf32.f32 "
        "{%0,%1,%2,%3}, {%4,%5,%6,%7}, {%8,%9}, {%0,%1,%2,%3};"
        : "+f"(c[0]), "+f"(c[1]), "+f"(c[2]), "+f"(c[3])
        : "r"(a0), "r"(a1), "r"(a2), "r"(a3), "r"(b0), "r"(b1));
}

// ---------------- one-hop monotone barrier (32 CTAs per group) ---------------
// arrive: fire-and-forget RED; wait: VOLATILE poll of monotone counter.
// (non-volatile __ldcg here was removable under forward-progress UB -> R15 bug)
__device__ __forceinline__ void bg_barrier2(unsigned* cnt, unsigned target) {
    __threadfence();                    // release this CTA's global stores
    __syncthreads();
    if (threadIdx.x == 0) {
        atomicAdd(cnt, 1u);             // result unused -> RED (no round trip)
        while (*(volatile unsigned*)cnt < target) { }
    }
    __syncthreads();
}

// ---------------- setup: maskf, x_mean, dt, counter reset --------------------
__global__ void k_setup(const float* __restrict__ C, const float* __restrict__ t,
                        const int* __restrict__ mask) {
    int b = blockIdx.x;
    int h = threadIdx.x;                 // 512
    float s1 = 0.f, s0 = 0.f;
    for (int i = 0; i < Ldim; i++) {
        size_t mi = ((size_t)b*Ldim + i)*Hdim + h;
        float m = (float)mask[mi];
        g_maskf[mi] = m;
        s1 += m * C[i*Hdim + h];
        s0 += m;
    }
    g_xmeanBH[b*Hdim + h] = s1 / fmaxf(s0, 1.f);
    if (h < Ldim) {
        int i = h;
        g_dtT[i*Bdim + b] = (i == 0) ? 0.f : (t[b*Ldim + i] - t[b*Ldim + i - 1]);
    }
    if (b == 0 && h < 4) { g_cnt1[h] = 0; g_cnt2[h] = 0; }
}

// ---------------- round weights to tf32 once ---------------------------------
__global__ void __launch_bounds__(1024) k_roundw(const float* __restrict__ Wx,
                                                 const float* __restrict__ Wm,
                                                 const float* __restrict__ Wh,
                                                 const float* __restrict__ Wgh) {
    int idx = blockIdx.x * 1024 + threadIdx.x;       // grid covers 786432
    g_WxR[idx] = __uint_as_float(f2tf32(Wx[idx]));
    g_WmR[idx] = __uint_as_float(f2tf32(Wm[idx]));
    g_WhR[idx] = __uint_as_float(f2tf32(Wh[idx]));
    if (idx < Hdim*Hdim)
        g_WghR[idx] = __uint_as_float(f2tf32(Wgh[idx]));
}

// ---------------- elementwise scan: delta[i], x_hat[i] (tf32-rounded) --------
__global__ void __launch_bounds__(512) k_scan(const float* __restrict__ C,
                                              const float* __restrict__ w_gx,
                                              const float* __restrict__ b_gx) {
    int gid = blockIdx.x * 512 + threadIdx.x;   // 65536
    int b = gid >> 9, h = gid & 511;
    float xm = g_xmeanBH[b*Hdim + h];
    float x_last = xm, delta = 0.f, m_prev = 1.f;
    float wg = __ldg(&w_gx[h]), bg = __ldg(&b_gx[h]);
    for (int i = 0; i < Ldim; i++) {
        float dti = g_dtT[i*Bdim + b];
        delta = dti + (1.f - m_prev) * delta;
        float m  = g_maskf[((size_t)b*Ldim + i)*Hdim + h];
        float xi = __ldg(&C[i*Hdim + h]);
        float gx = __expf(-fmaxf(0.f, wg*delta + bg));
        size_t idx = ((size_t)i*Bdim + b)*Hdim + h;
        float xh = m*xi + (1.f - m)*(gx*x_last + (1.f - gx)*xm);
        g_xhatS[idx]  = __uint_as_float(f2tf32(xh));
        g_deltaS[idx] = __uint_as_float(f2tf32(delta));
        x_last = m*xi + (1.f - m)*x_last;
        m_prev = m;
    }
    g_hsT[h*Bdim + b] = 0.f;   // h_scaled init (h0 = 0)
}

// ---------------- tf32 tensor GEMM: pre = [xhat;m] @ [Wx;Wm] + b -------------
// N-tile 64 (3 CTAs/SM). tile M=128(batch) N=64(cols) K=1024. 2-buffer.
#define PAD_A 36
#define PAD_B 72
#define PRE_SMEM ((2*128*PAD_A + 2*32*PAD_B)*4)
__global__ void __launch_bounds__(256, 3) k_pre(const float* __restrict__ bvec) {
    extern __shared__ float sm[];
    float* sA = sm;                     // 2 x 128 x 36
    float* sB = sm + 2*128*PAD_A;       // 2 x 32 x 72
    int ct = blockIdx.x, i = blockIdx.y, tid = threadIdx.x;
    int lane = tid & 31, warp = tid >> 5;
    int wm = warp & 1, wn = warp >> 1;   // wm: 2 M-halves, wn: 4 N-quarters

    auto loadA = [&](int ck, int buf) {
        int k0 = ck*32;
#pragma unroll
        for (int v = 0; v < 4; v++) {
            int idx = tid + v*256;
            int b = idx >> 3;
            int kq = (idx & 7) * 4;
            const float* src = (k0 < Hdim)
                ? g_xhatS + ((size_t)i*Bdim + b)*Hdim + k0 + kq
                : g_maskf + ((size_t)b*Ldim + i)*Hdim + (k0 - Hdim) + kq;
            cp16(sA + buf*128*PAD_A + b*PAD_A + kq, src);
        }
    };
    auto loadB = [&](int ck, int buf) {
        int k0 = ck*32;
#pragma unroll
        for (int v = 0; v < 2; v++) {
            int idx = tid + v*256;       // 0..511 (32 rows x 16 float4)
            int k = idx >> 4;
            int q = (idx & 15) * 4;
            const float* src = (k0 < Hdim
                ? g_WxR + (size_t)(k0 + k)*1536
                : g_WmR + (size_t)(k0 - Hdim + k)*1536) + ct*64 + q;
            cp16(sB + buf*32*PAD_B + k*PAD_B + q, src);
        }
    };

    float c[4][2][4] = {};
    loadA(0, 0); loadB(0, 0); CP_COMMIT;
    for (int ck = 0; ck < 32; ck++) {
        if (ck < 31) { loadA(ck+1, (ck+1)&1); loadB(ck+1, (ck+1)&1); CP_COMMIT; CP_WAIT1; }
        else         { CP_WAIT0; }
        __syncthreads();
        const float* A = sA + (ck&1)*128*PAD_A;
        const float* B = sB + (ck&1)*32*PAD_B;
#pragma unroll
        for (int ks = 0; ks < 4; ks++) {
            unsigned af[4][4], bf[2][2];
#pragma unroll
            for (int mi = 0; mi < 4; mi++) {
                int r  = wm*64 + mi*16 + (lane >> 2);
                int cc = ks*8 + (lane & 3);
                af[mi][0] = __float_as_uint(A[r*PAD_A + cc]);
                af[mi][1] = __float_as_uint(A[(r+8)*PAD_A + cc]);
                af[mi][2] = __float_as_uint(A[r*PAD_A + cc + 4]);
                af[mi][3] = __float_as_uint(A[(r+8)*PAD_A + cc + 4]);
            }
#pragma unroll
            for (int ni = 0; ni < 2; ni++) {
                int n  = wn*16 + ni*8 + (lane >> 2);
                int kk = ks*8 + (lane & 3);
                bf[ni][0] = __float_as_uint(B[kk*PAD_B + n]);
                bf[ni][1] = __float_as_uint(B[(kk+4)*PAD_B + n]);
            }
#pragma unroll
            for (int mi = 0; mi < 4; mi++)
#pragma unroll
                for (int ni = 0; ni < 2; ni++)
                    mma_tf32(c[mi][ni], af[mi][0], af[mi][1], af[mi][2], af[mi][3],
                             bf[ni][0], bf[ni][1]);
        }
        __syncthreads();
    }
#pragma unroll
    for (int mi = 0; mi < 4; mi++) {
        int r0 = wm*64 + mi*16 + (lane >> 2);
#pragma unroll
        for (int ni = 0; ni < 2; ni++) {
            int col0 = ct*64 + wn*16 + ni*8 + (lane & 3)*2;
            float bv0 = __ldg(&bvec[col0]);
            float bv1 = __ldg(&bvec[col0 + 1]);
            float* d0;
            float* d1;
            if (ct < 16) {
                d0 = g_preZ + (size_t)i*(2*Hdim*Bdim) + (size_t)col0*Bdim;
                d1 = d0 + Bdim;
            } else {
                d0 = g_preC + (size_t)i*(Hdim*Bdim) + (size_t)(col0 - 2*Hdim)*Bdim;
                d1 = d0 + Bdim;
            }
            d0[r0]     = c[mi][ni][0] + bv0;
            d1[r0]     = c[mi][ni][1] + bv1;
            d0[r0 + 8] = c[mi][ni][2] + bv0;
            d1[r0 + 8] = c[mi][ni][3] + bv1;
        }
    }
}

// ---------------- tf32 tensor GEMM: gamma = exp(-relu(delta@Wgh + b)) --------
// N-tile 64, grid (8, 256).
__global__ void __launch_bounds__(256, 3) k_gamma(const float* __restrict__ bgh) {
    extern __shared__ float sm[];
    float* sA = sm;
    float* sB = sm + 2*128*PAD_A;
    int ct = blockIdx.x, i = blockIdx.y, tid = threadIdx.x;
    int lane = tid & 31, warp = tid >> 5;
    int wm = warp & 1, wn = warp >> 1;

    auto loadA = [&](int ck, int buf) {
        int k0 = ck*32;
#pragma unroll
        for (int v = 0; v < 4; v++) {
            int idx = tid + v*256;
            int b = idx >> 3;
            int kq = (idx & 7) * 4;
            cp16(sA + buf*128*PAD_A + b*PAD_A + kq,
                 g_deltaS + ((size_t)i*Bdim + b)*Hdim + k0 + kq);
        }
    };
    auto loadB = [&](int ck, int buf) {
        int k0 = ck*32;
#pragma unroll
        for (int v = 0; v < 2; v++) {
            int idx = tid + v*256;
            int k = idx >> 4;
            int q = (idx & 15) * 4;
            cp16(sB + buf*32*PAD_B + k*PAD_B + q,
                 g_WghR + (size_t)(k0 + k)*Hdim + ct*64 + q);
        }
    };

    float c[4][2][4] = {};
    loadA(0, 0); loadB(0, 0); CP_COMMIT;
    for (int ck = 0; ck < 16; ck++) {
        if (ck < 15) { loadA(ck+1, (ck+1)&1); loadB(ck+1, (ck+1)&1); CP_COMMIT; CP_WAIT1; }
        else         { CP_WAIT0; }
        __syncthreads();
        const float* A = sA + (ck&1)*128*PAD_A;
        const float* B = sB + (ck&1)*32*PAD_B;
#pragma unroll
        for (int ks = 0; ks < 4; ks++) {
            unsigned af[4][4], bf[2][2];
#pragma unroll
            for (int mi = 0; mi < 4; mi++) {
                int r  = wm*64 + mi*16 + (lane >> 2);
                int cc = ks*8 + (lane & 3);
                af[mi][0] = __float_as_uint(A[r*PAD_A + cc]);
                af[mi][1] = __float_as_uint(A[(r+8)*PAD_A + cc]);
                af[mi][2] = __float_as_uint(A[r*PAD_A + cc + 4]);
                af[mi][3] = __float_as_uint(A[(r+8)*PAD_A + cc + 4]);
            }
#pragma unroll
            for (int ni = 0; ni < 2; ni++) {
                int n  = wn*16 + ni*8 + (lane >> 2);
                int kk = ks*8 + (lane & 3);
                bf[ni][0] = __float_as_uint(B[kk*PAD_B + n]);
                bf[ni][1] = __float_as_uint(B[(kk+4)*PAD_B + n]);
            }
#pragma unroll
            for (int mi = 0; mi < 4; mi++)
#pragma unroll
                for (int ni = 0; ni < 2; ni++)
                    mma_tf32(c[mi][ni], af[mi][0], af[mi][1], af[mi][2], af[mi][3],
                             bf[ni][0], bf[ni][1]);
        }
        __syncthreads();
    }
#pragma unroll
    for (int mi = 0; mi < 4; mi++) {
        int r0 = wm*64 + mi*16 + (lane >> 2);
#pragma unroll
        for (int ni = 0; ni < 2; ni++) {
            int col0 = ct*64 + wn*16 + ni*8 + (lane & 3)*2;
            float bv0 = __ldg(&bgh[col0]);
            float bv1 = __ldg(&bgh[col0 + 1]);
            float* d0 = g_gamma + (size_t)i*(Hdim*Bdim) + (size_t)col0*Bdim;
            float* d1 = d0 + Bdim;
            d0[r0]     = __expf(-fmaxf(0.f, c[mi][ni][0] + bv0));
            d1[r0]     = __expf(-fmaxf(0.f, c[mi][ni][1] + bv1));
            d0[r0 + 8] = __expf(-fmaxf(0.f, c[mi][ni][2] + bv0));
            d1[r0 + 8] = __expf(-fmaxf(0.f, c[mi][ni][3] + bv1));
        }
    }
}

// ============ persistent recurrence: tensor-core, 2xTF32, paired z/r =========
// 128 CTAs = 4 batch groups (32 batches) x 32 col groups.
// CTA cg owns z col (16cg+j), r col (512+16cg+j), cand col (1024+16cg+j), j<16.
#define SWH(k,b) ((k)*32 + ((b) ^ (((k)&3)<<3)))
#define SW3(k,n) ((k)*16 + ((n) ^ (((k)&2)<<2)))
#define OFF_H    0
#define OFF_WZR  16384
#define OFF_W3   32768
#define OFF_PART 40960
#define OFF_PZ   49408
#define OFF_PC   50432
#define OFF_GAM  50944
#define MAIN_SM_FLOATS 51456   // ~201 KB

__global__ void __launch_bounds__(512, 1) k_main() {
    extern __shared__ float sm[];
    float* smH   = sm + OFF_H;     // [512][32] swizzled (h_s / rh batch slice)
    float* sWzr  = sm + OFF_WZR;   // [512][32] swizzled: cols 0..15 = z, 16..31 = r
    float* sW3   = sm + OFF_W3;    // [512][16] swizzled
    float* sPart = sm + OFF_PART;  // K-group partials
    float* smPZ  = sm + OFF_PZ;    // preZ slice [32col][32b] (z then r cols)
    float* smPC  = sm + OFF_PC;    // preC slice [16col][32b]
    float* smGam = sm + OFF_GAM;   // gamma[i+1] slice [16col][32b]

    const int c   = blockIdx.x;
    const int tid = threadIdx.x;
    const int bg  = c & 3;
    const int cg  = c >> 2;
    const int lane = tid & 31, warp = tid >> 5;
    const int kg = warp >> 1, mh = warp & 1;
    const int r = lane >> 2, q = lane & 3;
    const int t64 = tid & 63;

    // one-time weight slices (pre-rounded tf32)
    for (int f = tid; f < 4096; f += 512) {          // Wh_zr: 512x32 (z|r paired)
        int k = f >> 3, n = (f & 7) * 4;
        int gcol = (n < 16) ? (cg*16 + n) : (512 + cg*16 + (n - 16));
        cp16(&sWzr[SWH(k, n)], &g_WhR[(size_t)k*1536 + gcol]);
    }
    for (int f = tid; f < 2048; f += 512) {          // Wh3: 512x16
        int k = f >> 2, n = (f & 3) * 4;
        cp16(&sW3[SW3(k, n)], &g_WhR[(size_t)k*1536 + 1024 + cg*16 + n]);
    }
    CP_COMMIT; CP_WAIT0;
    __syncthreads();

    for (int i = 0; i < Ldim; i++) {
        // ---- prefetch step-constant slices ----
        if (tid < 256) {
            int col = tid >> 3, b4 = (tid & 7) * 4;   // col 0..31 (z|r paired)
            int gcol = (col < 16) ? (cg*16 + col) : (512 + cg*16 + (col - 16));
            cp16(&smPZ[col*32 + b4],
                 &g_preZ[(size_t)i*131072 + (size_t)gcol*128 + bg*32 + b4]);
        } else if (tid < 384) {
            int f = tid - 256;
            int col = f >> 3, b4 = (f & 7) * 4;
            cp16(&smPC[col*32 + b4],
                 &g_preC[(size_t)i*65536 + (size_t)(cg*16 + col)*128 + bg*32 + b4]);
        } else if (i + 1 < Ldim) {
            int f = tid - 384;
            int col = f >> 3, b4 = (f & 7) * 4;
            cp16(&smGam[col*32 + b4],
                 &g_gamma[(size_t)(i+1)*65536 + (size_t)(cg*16 + col)*128 + bg*32 + b4]);
        }
        CP_COMMIT;

        // ---- pipelined stage of h_s: each warp-pair stages only its K-rows ----
#pragma unroll
        for (int j = 0; j < 8; j++) {
            int f = kg*512 + t64 + j*64;
            int k = f >> 3, nb = (f & 7) * 4;
            cp16(&smH[SWH(k, nb)], &g_hsT[k*128 + bg*32 + nb]);
        }
        CP_COMMIT; CP_WAIT0;
        asm volatile("bar.sync %0, 64;" :: "r"(kg + 1) : "memory");

        // ---- phase1 mma (2xTF32): C[32b x 32col(z|r)], hi pass then lo pass ----
        {
            float acc[4][4] = {};
#pragma unroll
            for (int ks = 0; ks < 8; ks++) {
                int ka = kg*64 + ks*8 + q;
                int kb = ka + 4;
                int row = mh*16 + r;
                float a0f = smH[SWH(ka, row)];
                float a1f = smH[SWH(ka, row + 8)];
                float a2f = smH[SWH(kb, row)];
                float a3f = smH[SWH(kb, row + 8)];
                unsigned ah0 = f2tf32(a0f), ah1 = f2tf32(a1f);
                unsigned ah2 = f2tf32(a2f), ah3 = f2tf32(a3f);
                unsigned bh0[4], bh1[4];
#pragma unroll
                for (int nt = 0; nt < 4; nt++) {
                    int n = nt*8 + r;
                    bh0[nt] = __float_as_uint(sWzr[SWH(ka, n)]);
                    bh1[nt] = __float_as_uint(sWzr[SWH(kb, n)]);
                }
#pragma unroll
                for (int nt = 0; nt < 4; nt++)
                    mma_tf32(acc[nt], ah0, ah1, ah2, ah3, bh0[nt], bh1[nt]);
                unsigned al0 = f2tf32(a0f - __uint_as_float(ah0));
                unsigned al1 = f2tf32(a1f - __uint_as_float(ah1));
                unsigned al2 = f2tf32(a2f - __uint_as_float(ah2));
                unsigned al3 = f2tf32(a3f - __uint_as_float(ah3));
#pragma unroll
                for (int nt = 0; nt < 4; nt++)
                    mma_tf32(acc[nt], al0, al1, al2, al3, bh0[nt], bh1[nt]);
            }
            float* P = sPart + kg*1056;
            int row = mh*16 + r;
#pragma unroll
            for (int nt = 0; nt < 4; nt++) {
                int col = nt*8 + 2*q;
                P[row*33 + col]       = acc[nt][0];
                P[row*33 + col + 1]   = acc[nt][1];
                P[(row+8)*33 + col]   = acc[nt][2];
                P[(row+8)*33 + col+1] = acc[nt][3];
            }
        }
        __syncthreads();
        // reduce 8 partials + activation; z and own h_s stay in registers
        float zreg, hsreg;
        {
            float s = 0.f;
#pragma unroll
            for (int g2 = 0; g2 < 8; g2++)
                s += sPart[g2*1056 + lane*33 + warp];
            s += smPZ[warp*32 + lane];
            zreg = 1.f / (1.f + __expf(-s));
            float s2 = 0.f;
#pragma unroll
            for (int g2 = 0; g2 < 8; g2++)
                s2 += sPart[g2*1056 + lane*33 + warp + 16];
            s2 += smPZ[(warp + 16)*32 + lane];
            float rg = 1.f / (1.f + __expf(-s2));
            hsreg = smH[SWH(cg*16 + warp, lane)];
            g_rhT[(cg*16 + warp)*128 + bg*32 + lane] = rg * hsreg;
        }
        bg_barrier2(&g_cnt1[bg], 32u*(unsigned)(i + 1));

        // ---- pipelined stage of rh ----
#pragma unroll
        for (int j = 0; j < 8; j++) {
            int f = kg*512 + t64 + j*64;
            int k = f >> 3, nb = (f & 7) * 4;
            cp16(&smH[SWH(k, nb)], &g_rhT[k*128 + bg*32 + nb]);
        }
        CP_COMMIT; CP_WAIT0;
        asm volatile("bar.sync %0, 64;" :: "r"(kg + 1) : "memory");

        // ---- phase2 mma (2xTF32): C[32b x 16col], hi pass then lo pass ----
        {
            float acc[2][4] = {};
#pragma unroll
            for (int ks = 0; ks < 8; ks++) {
                int ka = kg*64 + ks*8 + q;
                int kb = ka + 4;
                int row = mh*16 + r;
                float a0f = smH[SWH(ka, row)];
                float a1f = smH[SWH(ka, row + 8)];
                float a2f = smH[SWH(kb, row)];
                float a3f = smH[SWH(kb, row + 8)];
                unsigned ah0 = f2tf32(a0f), ah1 = f2tf32(a1f);
                unsigned ah2 = f2tf32(a2f), ah3 = f2tf32(a3f);
                unsigned bh0[2], bh1[2];
#pragma unroll
                for (int nt = 0; nt < 2; nt++) {
                    int n = nt*8 + r;
                    bh0[nt] = __float_as_uint(sW3[SW3(ka, n)]);
                    bh1[nt] = __float_as_uint(sW3[SW3(kb, n)]);
                }
#pragma unroll
                for (int nt = 0; nt < 2; nt++)
                    mma_tf32(acc[nt], ah0, ah1, ah2, ah3, bh0[nt], bh1[nt]);
                unsigned al0 = f2tf32(a0f - __uint_as_float(ah0));
                unsigned al1 = f2tf32(a1f - __uint_as_float(ah1));
                unsigned al2 = f2tf32(a2f - __uint_as_float(ah2));
                unsigned al3 = f2tf32(a3f - __uint_as_float(ah3));
#pragma unroll
                for (int nt = 0; nt < 2; nt++)
                    mma_tf32(acc[nt], al0, al1, al2, al3, bh0[nt], bh1[nt]);
            }
            float* P = sPart + kg*544;
            int row = mh*16 + r;
#pragma unroll
            for (int nt = 0; nt < 2; nt++) {
                int col = nt*8 + 2*q;
                P[row*17 + col]       = acc[nt][0];
                P[row*17 + col + 1]   = acc[nt][1];
                P[(row+8)*17 + col]   = acc[nt][2];
                P[(row+8)*17 + col+1] = acc[nt][3];
            }
        }
        __syncthreads();
        // reduce + h update (col = warp, b = lane; z/h_s are registers)
        {
            float s = 0.f;
#pragma unroll
            for (int g2 = 0; g2 < 8; g2++)
                s += sPart[g2*544 + lane*17 + warp];
            float ht = tanhf(s + smPC[warp*32 + lane]);
            float hn = (1.f - zreg)*hsreg + zreg*ht;
            int gi = (cg*16 + warp)*128 + bg*32 + lane;
            g_hseq[(size_t)i*65536 + gi] = hn;
            if (i + 1 < Ldim)
                g_hsT[gi] = hn * smGam[warp*32 + lane];
        }
        bg_barrier2(&g_cnt2[bg], 32u*(unsigned)(i + 1));
    }
}

// ---------------- tf32 output GEMM: out = h_seq @ W_out + b_out --------------
#define OUT_SMEM (3*(4096+4096)*4)
__global__ void __launch_bounds__(256, 2) k_out(const float* __restrict__ Wout,
                                                const float* __restrict__ bout,
                                                float* __restrict__ out) {
    extern __shared__ float sm[];
    float* sA = sm;            // 3 x [32k][128b] swizzled
    float* sB = sm + 3*4096;   // 3 x [32k][128n] swizzled
    int ct = blockIdx.x, i = blockIdx.y, tid = threadIdx.x;
    int lane = tid & 31, warp = tid >> 5;
    int wm = warp & 1, wn = warp >> 1;

    auto loadA = [&](int ck, int buf) {
#pragma unroll
        for (int v = 0; v < 4; v++) {
            int f = tid + v*256;
            int k = f >> 5, nb = (f & 31) * 4;
            cp16(&sA[buf*4096 + k*128 + (nb ^ ((k & 3) << 3))],
                 &g_hseq[(size_t)i*65536 + (size_t)(ck*32 + k)*128 + nb]);
        }
    };
    auto loadB = [&](int ck, int buf) {
#pragma unroll
        for (int v = 0; v < 4; v++) {
            int f = tid + v*256;
            int k = f >> 5, nb = (f & 31) * 4;
            cp16(&sB[buf*4096 + k*128 + (nb ^ ((k & 3) << 3))],
                 &Wout[(size_t)(ck*32 + k)*OUTdim + ct*128 + nb]);
        }
    };

    float c[4][4][4] = {};
    loadA(0, 0); loadB(0, 0); CP_COMMIT;
    loadA(1, 1); loadB(1, 1); CP_COMMIT;
    for (int ck = 0; ck < 16; ck++) {
        if (ck < 15) { CP_WAIT1; } else { CP_WAIT0; }
        __syncthreads();
        if (ck + 2 < 16) { loadA(ck+2, (ck+2)%3); loadB(ck+2, (ck+2)%3); CP_COMMIT; }
        const float* A = sA + (ck%3)*4096;
        const float* B = sB + (ck%3)*4096;
#pragma unroll
        for (int ks = 0; ks < 4; ks++) {
            int ka = ks*8 + (lane & 3);
            int kb = ka + 4;
            unsigned af[4][4], bf[4][2];
#pragma unroll
            for (int mi = 0; mi < 4; mi++) {
                int b0 = wm*64 + mi*16 + (lane >> 2);
                af[mi][0] = f2tf32(A[ka*128 + (b0 ^ ((ka & 3) << 3))]);
                af[mi][1] = f2tf32(A[ka*128 + ((b0+8) ^ ((ka & 3) << 3))]);
                af[mi][2] = f2tf32(A[kb*128 + (b0 ^ ((kb & 3) << 3))]);
                af[mi][3] = f2tf32(A[kb*128 + ((b0+8) ^ ((kb & 3) << 3))]);
            }
#pragma unroll
            for (int ni = 0; ni < 4; ni++) {
                int n = wn*32 + ni*8 + (lane >> 2);
                bf[ni][0] = f2tf32(B[ka*128 + (n ^ ((ka & 3) << 3))]);
                bf[ni][1] = f2tf32(B[kb*128 + (n ^ ((kb & 3) << 3))]);
            }
#pragma unroll
            for (int mi = 0; mi < 4; mi++)
#pragma unroll
                for (int ni = 0; ni < 4; ni++)
                    mma_tf32(c[mi][ni], af[mi][0], af[mi][1], af[mi][2], af[mi][3],
                             bf[ni][0], bf[ni][1]);
        }
    }
#pragma unroll
    for (int mi = 0; mi < 4; mi++) {
        int r0 = wm*64 + mi*16 + (lane >> 2);
#pragma unroll
        for (int ni = 0; ni < 4; ni++) {
            int o0 = ct*128 + wn*32 + ni*8 + (lane & 3)*2;
            float bv0 = __ldg(&bout[o0]);
            float bv1 = __ldg(&bout[o0 + 1]);
            out[((size_t)r0*Ldim + i)*OUTdim + o0]         = c[mi][ni][0] + bv0;
            out[((size_t)r0*Ldim + i)*OUTdim + o0 + 1]     = c[mi][ni][1] + bv1;
            out[((size_t)(r0+8)*Ldim + i)*OUTdim + o0]     = c[mi][ni][2] + bv0;
            out[((size_t)(r0+8)*Ldim + i)*OUTdim + o0 + 1] = c[mi][ni][3] + bv1;
        }
    }
}

// ---------------- launch ------------------------------------------------------
extern "C" void kernel_launch(void* const* d_in, const int* in_sizes, int n_in,
                              void* d_out, int out_size) {
    const float* C    = (const float*)d_in[0];
    const float* t    = (const float*)d_in[1];
    const int*   mask = (const int*)  d_in[2];
    const float* Wx   = (const float*)d_in[3];
    const float* Wh   = (const float*)d_in[4];
    const float* Wm   = (const float*)d_in[5];
    const float* bvec = (const float*)d_in[6];
    const float* wgx  = (const float*)d_in[7];
    const float* bgx  = (const float*)d_in[8];
    const float* Wgh  = (const float*)d_in[9];
    const float* bgh  = (const float*)d_in[10];
    const float* Wout = (const float*)d_in[11];
    const float* bout = (const float*)d_in[12];
    float* out = (float*)d_out;

    cudaFuncSetAttribute(k_main, cudaFuncAttributeMaxDynamicSharedMemorySize,
                         MAIN_SM_FLOATS * 4);
    cudaFuncSetAttribute(k_pre, cudaFuncAttributeMaxDynamicSharedMemorySize, PRE_SMEM);
    cudaFuncSetAttribute(k_gamma, cudaFuncAttributeMaxDynamicSharedMemorySize, PRE_SMEM);
    cudaFuncSetAttribute(k_out, cudaFuncAttributeMaxDynamicSharedMemorySize, OUT_SMEM);

    k_setup<<<Bdim, Hdim>>>(C, t, mask);
    k_roundw<<<768, 1024>>>(Wx, Wm, Wh, Wgh);
    k_scan<<<128, 512>>>(C, wgx, bgx);
    k_pre<<<dim3(24, Ldim), 256, PRE_SMEM>>>(bvec);
    k_gamma<<<dim3(8, Ldim), 256, PRE_SMEM>>>(bgh);
    k_main<<<NCTA, 512, MAIN_SM_FLOATS * 4>>>();
    k_out<<<dim3(2, Ldim), 256, OUT_SMEM>>>(Wout, bout, out);
}